// round 7
// baseline (speedup 1.0000x reference)
#include <cuda_runtime.h>
#include <math.h>

// inv+1 map: flat rep id -> (AO row + 1); 0 = hole. Zero-init at module load;
// hole slots never written; scatter is collision-free & replay-idempotent.
__device__ int g_inv1[16384];

__global__ void scatter_inv_kernel(const int* __restrict__ ids, int n_ao) {
    int t = blockIdx.x * blockDim.x + threadIdx.x;
    if (t < n_ao) g_inv1[ids[t]] = t + 1;
}

// out[a1][a2][r1][r2] = feat[inv[a1*14+r1]][inv[a2*14+r2]]  (0 on hole)
//
// Block = (a1, chunk of CH consecutive a2 atoms). Atom AO ids are consecutive,
// so the block's feat needs are ONE contiguous sub-block (<=14 rows x <=CH*14
// cols): stage it coalesced into smem (each feat element staged exactly once
// across the grid), permute via LDS, emit coalesced STG.128.
// Emit uses fixed thread binding (q = tid%49 -> four fixed (r1,r2) slots), so
// the hot loop is 4 LDS(lc) + 4 LDS(tile) + 1 STG.128, zero divisions.
#define CH 28
#define WMAX (CH * 14)       // 392
#define TS 397               // tile row stride, odd -> spreads banks
#define NTHREADS 512
#define NGROUP 10            // emit groups (49 threads each, 490 active)

__global__ __launch_bounds__(NTHREADS) void gather_kernel(
    const float* __restrict__ feat,
    float4* __restrict__ out,
    unsigned n_ao, unsigned n_atoms) {

    __shared__ float tile[14 * TS];          // 22232 B
    __shared__ int s_lc[CH * 14];            // local col per (a2l, r2), -1 hole
    __shared__ int s_li[14];                 // local row per r1, -1 hole
    __shared__ int s_red[4];                 // rowMin1, rowMax1, colMin1, colMax1

    const unsigned a1 = blockIdx.y;
    const unsigned a2_lo = blockIdx.x * CH;
    const unsigned nA2 = min((unsigned)CH, n_atoms - a2_lo);
    const unsigned tid = threadIdx.x;

    if (tid == 0) { s_red[0] = 0x7fffffff; s_red[1] = 0; s_red[2] = 0x7fffffff; s_red[3] = 0; }
    int rawj = 0, rawi = 0;
    if (tid < nA2 * 14u)                 rawj = g_inv1[a2_lo * 14u + tid];
    if (tid >= 448u && tid < 462u)       rawi = g_inv1[a1 * 14u + (tid - 448u)];
    __syncthreads();
    if (rawj > 0) { atomicMin(&s_red[2], rawj); atomicMax(&s_red[3], rawj); }
    if (rawi > 0) { atomicMin(&s_red[0], rawi); atomicMax(&s_red[1], rawi); }
    __syncthreads();

    const int rowBase = s_red[0] - 1;                 // first feat row
    const int H       = s_red[1] - s_red[0] + 1;      // <= 14
    const int colBase = s_red[2] - 1;                 // first feat col
    const int W       = s_red[3] - s_red[2] + 1;      // <= 392

    if (tid < CH * 14u)
        s_lc[tid] = (tid < nA2 * 14u && rawj > 0) ? (rawj - 1 - colBase) : -1;
    if (tid >= 448u && tid < 462u)
        s_li[tid - 448u] = (rawi > 0) ? (rawi - 1 - rowBase) : -1;
    __syncthreads();

    // stage feat sub-block, row by row, coalesced
    for (int r = 0; r < H; ++r) {
        const float* src = feat + (size_t)(rowBase + r) * n_ao + colBase;
        for (unsigned c = tid; c < (unsigned)W; c += NTHREADS)
            tile[r * TS + c] = __ldg(src + c);
    }
    __syncthreads();

    // emit
    if (tid >= NGROUP * 49u) return;
    const unsigned q = tid % 49u;                     // fixed float4 slot
    const unsigned g = tid / 49u;                     // emit group 0..9

    int r2k[4], lik[4];
#pragma unroll
    for (int k = 0; k < 4; ++k) {
        const unsigned rr = q * 4u + (unsigned)k;     // 0..195
        const unsigned r1 = rr / 14u;
        r2k[k] = (int)(rr - r1 * 14u);
        lik[k] = s_li[r1];
    }

    float4* dst = out + ((size_t)a1 * n_atoms + a2_lo + g) * 49u + q;
    for (unsigned a2l = g; a2l < nA2; a2l += NGROUP) {
        const int* lcrow = s_lc + a2l * 14u;
        float4 v;
        float* vf = (float*)&v;
#pragma unroll
        for (int k = 0; k < 4; ++k) {
            const int lc = lcrow[r2k[k]];
            const int li = lik[k];
            vf[k] = ((li | lc) >= 0) ? tile[li * TS + lc] : 0.0f;
        }
        *dst = v;
        dst += (size_t)NGROUP * 49u;
    }
}

extern "C" void kernel_launch(void* const* d_in, const int* in_sizes, int n_in,
                              void* d_out, int out_size) {
    const float* feat = (const float*)d_in[0];
    const int*   ids  = (const int*)d_in[1];

    const int n_ao = in_sizes[1];               // 5800
    const int R    = 14;                        // num_reps_1d
    const int a2r  = out_size / (R * R);        // A^2
    const int A    = (int)(sqrtf((float)a2r) + 0.5f);   // 500
    (void)n_ao;

    scatter_inv_kernel<<<(n_ao + 255) / 256, 256>>>(ids, n_ao);

    dim3 grid((A + CH - 1) / CH, A);            // 18 x 500
    gather_kernel<<<grid, NTHREADS>>>(feat, (float4*)d_out,
                                      (unsigned)n_ao, (unsigned)A);
}